// round 2
// baseline (speedup 1.0000x reference)
#include <cuda_runtime.h>
#include <cstdint>

#define N_NODES 8192
#define N_EDGES 8192
#define DEG     32
#define NNZ     (N_EDGES * DEG)
#define D       32

// Scratch (no device allocation allowed; __device__ globals are the sanctioned path)
__device__ float g_M0[D];
__device__ float g_M1[D];
__device__ float g_c;
__device__ float g_p[N_NODES * 2];   // p[n] = x_0[n] @ M  (2 comps interleaved)
__device__ float g_y[N_NODES * 2];   // y[n] = sum_{e∋n} z[e]
__device__ float g_a[N_NODES];       // a[n] = sum_{e∋n} t[e].0
__device__ float g_b[N_EDGES];       // b[e] = t[e].1

// ---------------------------------------------------------------------------
// Fold the whole affine chain into M (32x2) and scalar c.
//   q   = Wm2 @ Wm3                         (32)
//   u,v = split(Wm1 @ q, 32)                (32 each)
//   c   = bm1·q + bm2·Wm3 + bm3
//   w2u = W_l2 @ u
//   M   = W_l1 @ [w2u | v]
// ---------------------------------------------------------------------------
__global__ void k_const(const float* __restrict__ Wl1, const float* __restrict__ Wl2,
                        const float* __restrict__ Wm1, const float* __restrict__ bm1,
                        const float* __restrict__ Wm2, const float* __restrict__ bm2,
                        const float* __restrict__ Wm3, const float* __restrict__ bm3) {
    __shared__ float q[D], u[D], v[D], w2u[D];
    const int k = threadIdx.x;
    if (k < D) {
        float s = 0.f;
        #pragma unroll
        for (int j = 0; j < D; ++j) s += Wm2[k * D + j] * Wm3[j];
        q[k] = s;
    }
    __syncthreads();
    if (k < D) {
        float su = 0.f, sv = 0.f;
        #pragma unroll
        for (int j = 0; j < D; ++j) {
            su += Wm1[k * D + j] * q[j];
            sv += Wm1[(D + k) * D + j] * q[j];
        }
        u[k] = su; v[k] = sv;
    }
    __syncthreads();
    if (k == 0) {
        float c = bm3[0];
        #pragma unroll
        for (int j = 0; j < D; ++j) c += bm1[j] * q[j] + bm2[j] * Wm3[j];
        g_c = c;
    }
    if (k < D) {
        float s = 0.f;
        #pragma unroll
        for (int j = 0; j < D; ++j) s += Wl2[k * D + j] * u[j];
        w2u[k] = s;
    }
    __syncthreads();
    if (k < D) {
        float s0 = 0.f, s1 = 0.f;
        #pragma unroll
        for (int j = 0; j < D; ++j) {
            s0 += Wl1[k * D + j] * w2u[j];
            s1 += Wl1[k * D + j] * v[j];
        }
        g_M0[k] = s0; g_M1[k] = s1;
    }
}

// ---------------------------------------------------------------------------
// p[n] = x_0[n] @ M ; also zero the accumulators for this launch.
// ---------------------------------------------------------------------------
__global__ void k_p(const float* __restrict__ x0) {
    const int n = blockIdx.x * blockDim.x + threadIdx.x;
    if (n >= N_NODES) return;
    const float* row = x0 + (size_t)n * D;
    float p0 = 0.f, p1 = 0.f;
    #pragma unroll
    for (int j = 0; j < D; ++j) {
        const float x = row[j];
        p0 += x * g_M0[j];
        p1 += x * g_M1[j];
    }
    g_p[2 * n]     = p0;
    g_p[2 * n + 1] = p1;
    g_y[2 * n]     = 0.f;
    g_y[2 * n + 1] = 0.f;
    g_a[n]         = 0.f;
}

// Warp-per-edge: unique-gather-sum of src2 over the edge's nodes, then
// scatter-add the edge sum back to the nodes (dst2), both deduped.
__device__ __forceinline__ void edge_pass(const int* __restrict__ node_idx,
                                          const float* __restrict__ src2,
                                          float* __restrict__ dst2,
                                          float* __restrict__ edge_out, // may be null
                                          float* __restrict__ dst1)    // may be null
{
    const int tid  = blockIdx.x * blockDim.x + threadIdx.x;
    const int e    = tid >> 5;
    const int lane = threadIdx.x & 31;
    if (e >= N_EDGES) return;

    const int n = node_idx[e * DEG + lane];
    const unsigned peers = __match_any_sync(0xffffffffu, n);
    const bool keep = (peers & ((1u << lane) - 1u)) == 0u;  // first occurrence in edge

    float s0 = 0.f, s1 = 0.f;
    if (keep) {
        const float2 pv = *(const float2*)&src2[2 * n];
        s0 = pv.x; s1 = pv.y;
    }
    #pragma unroll
    for (int o = 16; o > 0; o >>= 1) {
        s0 += __shfl_xor_sync(0xffffffffu, s0, o);
        s1 += __shfl_xor_sync(0xffffffffu, s1, o);
    }
    if (edge_out && lane == 0) edge_out[e] = s1;
    if (dst2 && keep) {
        atomicAdd(&dst2[2 * n],     s0);
        atomicAdd(&dst2[2 * n + 1], s1);
    }
    if (dst1 && keep) {
        atomicAdd(&dst1[n], s0);
    }
}

// z[e] = Σ_{n∈e} p[n] ; y[n] += z[e]
__global__ void k_zy(const int* __restrict__ node_idx) {
    edge_pass(node_idx, g_p, g_y, nullptr, nullptr);
}

// t[e] = Σ_{n∈e} y[n] ; b[e] = t.1 ; a[n] += t.0
__global__ void k_ta(const int* __restrict__ node_idx) {
    edge_pass(node_idx, g_y, nullptr, g_b, g_a);
}

// out[n, e] = a[n] + b[e] + c at nnz positions (duplicates write same value)
__global__ void k_out(const int* __restrict__ node_idx, float* __restrict__ out) {
    const int i = blockIdx.x * blockDim.x + threadIdx.x;
    if (i >= NNZ) return;
    const int n = node_idx[i];
    const int e = i >> 5;  // edge_idx = repeat(arange(E), DEG) by construction
    out[(size_t)n * N_EDGES + e] = g_a[n] + g_b[e] + g_c;
}

extern "C" void kernel_launch(void* const* d_in, const int* in_sizes, int n_in,
                              void* d_out, int out_size) {
    const float* x0   = (const float*)d_in[0];
    // d_in[1] = incidence_1 (dense)  -- unused, we use the index lists
    const float* Wl1  = (const float*)d_in[2];
    const float* Wl2  = (const float*)d_in[3];
    const float* Wm1  = (const float*)d_in[4];
    const float* bm1  = (const float*)d_in[5];
    const float* Wm2  = (const float*)d_in[6];
    const float* bm2  = (const float*)d_in[7];
    const float* Wm3  = (const float*)d_in[8];
    const float* bm3  = (const float*)d_in[9];
    const int*   nidx = (const int*)d_in[10];
    // d_in[11] = edge_idx -- implied by position (i >> 5)

    float* out = (float*)d_out;

    // Zero the 256 MB output (bandwidth-dominant step).
    cudaMemsetAsync(out, 0, (size_t)out_size * sizeof(float));

    k_const<<<1, 32>>>(Wl1, Wl2, Wm1, bm1, Wm2, bm2, Wm3, bm3);
    k_p<<<N_NODES / 256, 256>>>(x0);
    k_zy<<<NNZ / 256, 256>>>(nidx);
    k_ta<<<NNZ / 256, 256>>>(nidx);
    k_out<<<NNZ / 256, 256>>>(nidx, out);
}